// round 10
// baseline (speedup 1.0000x reference)
#include <cuda_runtime.h>
#include <cuda_fp16.h>
#include <cstdint>

#define N_ROWS 8192
#define FFN    4096
#define EMB    1024

#define CHUNKS    4
#define CHUNK_ROWS (N_ROWS / CHUNKS)            // 2048

// ---------------- HMMA GEMM config ----------------
#define BM 128
#define BN 128
#define BK 64
#define STAGES 3
#define KITERS (FFN / BK)                       // 64
#define A_STAGE_BYTES (BM * BK * 2)             // 16 KB
#define B_STAGE_BYTES (BN * BK * 2)             // 16 KB
#define STAGE_BYTES (A_STAGE_BYTES + B_STAGE_BYTES)   // 32 KB
#define SMEM_TOTAL (STAGES * STAGE_BYTES)       // 96 KB -> 2 CTAs/SM

#define GELU_BLOCKS_CHUNK 4096                  // 2048*4096 / (256*8)
#define WCONV_BLOCKS 4096                       // 4.19M / (256*4)

// Static scratch (allocation-free rule)
__device__ __align__(16) __half g_h[(size_t)N_ROWS * FFN];   // gelu(x)*mask*scale
__device__ __align__(16) __half g_w[(size_t)EMB * FFN];      // weight fp16
__device__ __align__(16) __half g_bias[EMB];

// ---------------------------------------------------------------------------
// Warp-local sniff: classify buffer order + dtype scenario from 32 words each.
// ---------------------------------------------------------------------------
__device__ __forceinline__ void sniff(const unsigned* A, const unsigned* B,
                                      int& sw, int& f32) {
    int lane = threadIdx.x & 31;
    unsigned a = __ldg(A + lane);
    unsigned b = __ldg(B + lane);
    unsigned wa = __ballot_sync(~0u, a <= 1u);
    unsigned wb = __ballot_sync(~0u, b <= 1u);
    unsigned ba = __ballot_sync(~0u, (a & 0xFEFEFEFEu) == 0u);
    unsigned bb = __ballot_sync(~0u, (b & 0xFEFEFEFEu) == 0u);
    if      (wb == ~0u) { sw = 0; f32 = 1; }
    else if (wa == ~0u) { sw = 1; f32 = 1; }
    else if (bb == ~0u) { sw = 0; f32 = 0; }
    else if (ba == ~0u) { sw = 1; f32 = 0; }
    else                { sw = 0; f32 = 1; }
}

// ---------------------------------------------------------------------------
// Prep chunk: gelu rows [rowOff, rowOff+2048) -> g_h ; chunk 0 also W + bias
// ---------------------------------------------------------------------------
__global__ void __launch_bounds__(256) prep_k(const void* __restrict__ A,
                                              const void* __restrict__ B,
                                              const void* __restrict__ w,
                                              const void* __restrict__ bias,
                                              int rowOff, int withW) {
    int sw, f32;
    sniff((const unsigned*)A, (const unsigned*)B, sw, f32);

    unsigned bidx = blockIdx.x;
    if (bidx < GELU_BLOCKS_CHUNK) {
        const char* xp = (const char*)(sw ? B : A);
        const char* mp = (const char*)(sw ? A : B);
        size_t idx = (size_t)rowOff * FFN + ((size_t)bidx * 256 + threadIdx.x) * 8;

        float xf[8];
        unsigned char keep[8];
        if (f32) {
            const float4* xv = (const float4*)(xp + idx * 4);
            float4 v0 = xv[0], v1 = xv[1];
            xf[0]=v0.x; xf[1]=v0.y; xf[2]=v0.z; xf[3]=v0.w;
            xf[4]=v1.x; xf[5]=v1.y; xf[6]=v1.z; xf[7]=v1.w;
            const int4* mv = (const int4*)(mp + idx * 4);
            int4 m0 = mv[0], m1 = mv[1];
            keep[0]=(unsigned char)m0.x; keep[1]=(unsigned char)m0.y;
            keep[2]=(unsigned char)m0.z; keep[3]=(unsigned char)m0.w;
            keep[4]=(unsigned char)m1.x; keep[5]=(unsigned char)m1.y;
            keep[6]=(unsigned char)m1.z; keep[7]=(unsigned char)m1.w;
        } else {
            uint4 hv = *(const uint4*)(xp + idx * 2);
            __half hs[8]; *reinterpret_cast<uint4*>(hs) = hv;
#pragma unroll
            for (int i = 0; i < 8; i++) xf[i] = __half2float(hs[i]);
            uint2 mb = *(const uint2*)(mp + idx);
            *reinterpret_cast<uint2*>(keep) = mb;
        }

        const __half sc = __float2half(1.0f / 0.9f);
        __half hs[8];
#pragma unroll
        for (int i = 0; i < 8; i++) {
            float g  = 0.5f * xf[i] * (1.0f + erff(xf[i] * 0.70710678118654752440f));
            __half gh = __float2half(g);
            hs[i] = keep[i] ? __hmul(gh, sc) : __ushort_as_half((unsigned short)0);
        }
        *reinterpret_cast<uint4*>(g_h + idx) = *reinterpret_cast<uint4*>(hs);
    } else if (withW && bidx < GELU_BLOCKS_CHUNK + WCONV_BLOCKS) {
        size_t i = ((size_t)(bidx - GELU_BLOCKS_CHUNK) * 256 + threadIdx.x) * 4;
        if (f32) {
            float4 v = *(const float4*)((const float*)w + i);
            __half h[4] = {__float2half(v.x), __float2half(v.y),
                           __float2half(v.z), __float2half(v.w)};
            *reinterpret_cast<uint2*>(g_w + i) = *reinterpret_cast<uint2*>(h);
        } else {
            *reinterpret_cast<uint2*>(g_w + i) = *(const uint2*)((const __half*)w + i);
        }
    } else if (withW) {
        int i = threadIdx.x * 4;
        if (i < EMB) {
            if (f32) {
                float4 v = *(const float4*)((const float*)bias + i);
                __half h[4] = {__float2half(v.x), __float2half(v.y),
                               __float2half(v.z), __float2half(v.w)};
                *reinterpret_cast<uint2*>(g_bias + i) = *reinterpret_cast<uint2*>(h);
            } else {
                *reinterpret_cast<uint2*>(g_bias + i) = *(const uint2*)((const __half*)bias + i);
            }
        }
    }
}

// ---------------------------------------------------------------------------
// GEMM chunk: rows [mOff, mOff+2048) : y = g_h @ g_w^T + bias
// 256 threads = 8 warps (2x4), warp tile 64x32, 3-stage cp.async, 2 CTAs/SM.
// ---------------------------------------------------------------------------
__global__ void __launch_bounds__(256, 2) gemm_k(void* __restrict__ outv,
                                                 const void* __restrict__ A0,
                                                 const void* __restrict__ B0,
                                                 int mOff) {
    extern __shared__ __align__(1024) char sm[];
    const uint32_t smem_base = (uint32_t)__cvta_generic_to_shared(sm);

    int snsw, f32o;
    sniff((const unsigned*)A0, (const unsigned*)B0, snsw, f32o);

    const int tid  = threadIdx.x;
    const int lane = tid & 31;
    const int warp = tid >> 5;
    const int wm   = (warp >> 2) * 64;
    const int wn   = (warp & 3) * 32;

    const int mBase = mOff + blockIdx.y * BM;
    const int nBase = blockIdx.x * BN;

    const __half* Aglob = g_h + (size_t)mBase * FFN;
    const __half* Bglob = g_w + (size_t)nBase * FFN;

    float acc[4][4][4];
#pragma unroll
    for (int a = 0; a < 4; a++)
#pragma unroll
        for (int b = 0; b < 4; b++)
#pragma unroll
            for (int c = 0; c < 4; c++) acc[a][b][c] = 0.f;

    auto swz = [](uint32_t off) -> uint32_t { return off ^ ((off >> 3) & 0x70); };

    auto fill = [&](int kt) {
        int buf = kt % STAGES;
        uint32_t sA = smem_base + buf * STAGE_BYTES;
        uint32_t sB = sA + A_STAGE_BYTES;
        const __half* Ag = Aglob + kt * BK;
        const __half* Bg = Bglob + kt * BK;
#pragma unroll
        for (int i = 0; i < 4; i++) {
            int idx = tid + (i << 8);
            int row = idx >> 3, c = idx & 7;
            uint32_t off = (uint32_t)(row * 128 + c * 16);
            asm volatile("cp.async.cg.shared.global [%0], [%1], 16;"
                         :: "r"(sA + (off ^ ((off >> 3) & 0x70))),
                            "l"(Ag + (size_t)row * FFN + c * 8));
        }
#pragma unroll
        for (int i = 0; i < 4; i++) {
            int idx = tid + (i << 8);
            int row = idx >> 3, c = idx & 7;
            uint32_t off = (uint32_t)(row * 128 + c * 16);
            asm volatile("cp.async.cg.shared.global [%0], [%1], 16;"
                         :: "r"(sB + (off ^ ((off >> 3) & 0x70))),
                            "l"(Bg + (size_t)row * FFN + c * 8));
        }
        asm volatile("cp.async.commit_group;");
    };

    fill(0); fill(1);

    for (int kt = 0; kt < KITERS; ++kt) {
        if (kt + 1 < KITERS) asm volatile("cp.async.wait_group 1;");
        else                 asm volatile("cp.async.wait_group 0;");
        __syncthreads();

        // Prefetch early: target buffer's readers all passed the sync above.
        if (kt + STAGES - 1 < KITERS) fill(kt + STAGES - 1);

        int buf = kt % STAGES;
        uint32_t sA = smem_base + buf * STAGE_BYTES;
        uint32_t sB = sA + A_STAGE_BYTES;

#pragma unroll
        for (int ks = 0; ks < 4; ks++) {
            uint32_t a[4][4];
#pragma unroll
            for (int mi = 0; mi < 4; mi++) {
                int r = wm + mi * 16 + ((lane >> 3) & 1) * 8 + (lane & 7);
                int c = ks * 16 + (lane >> 4) * 8;
                uint32_t addr = sA + swz((uint32_t)(r * 128 + c * 2));
                asm volatile("ldmatrix.sync.aligned.m8n8.x4.shared.b16 {%0,%1,%2,%3}, [%4];"
                             : "=r"(a[mi][0]), "=r"(a[mi][1]), "=r"(a[mi][2]), "=r"(a[mi][3])
                             : "r"(addr));
            }
            uint32_t b[4][2];
#pragma unroll
            for (int nj = 0; nj < 2; nj++) {
                int r = wn + nj * 16 + (lane >> 4) * 8 + (lane & 7);
                int c = ks * 16 + ((lane >> 3) & 1) * 8;
                uint32_t addr = sB + swz((uint32_t)(r * 128 + c * 2));
                asm volatile("ldmatrix.sync.aligned.m8n8.x4.shared.b16 {%0,%1,%2,%3}, [%4];"
                             : "=r"(b[2 * nj][0]), "=r"(b[2 * nj][1]),
                               "=r"(b[2 * nj + 1][0]), "=r"(b[2 * nj + 1][1])
                             : "r"(addr));
            }
#pragma unroll
            for (int mi = 0; mi < 4; mi++)
#pragma unroll
                for (int ni = 0; ni < 4; ni++) {
                    asm volatile(
                        "mma.sync.aligned.m16n8k16.row.col.f32.f16.f16.f32 "
                        "{%0,%1,%2,%3}, {%4,%5,%6,%7}, {%8,%9}, {%0,%1,%2,%3};"
                        : "+f"(acc[mi][ni][0]), "+f"(acc[mi][ni][1]),
                          "+f"(acc[mi][ni][2]), "+f"(acc[mi][ni][3])
                        : "r"(a[mi][0]), "r"(a[mi][1]), "r"(a[mi][2]), "r"(a[mi][3]),
                          "r"(b[ni][0]), "r"(b[ni][1]));
                }
        }
    }

    // Epilogue
#pragma unroll
    for (int mi = 0; mi < 4; mi++) {
#pragma unroll
        for (int ni = 0; ni < 4; ni++) {
            int row = mBase + wm + mi * 16 + (lane >> 2);
            int col = nBase + wn + ni * 8 + (lane & 3) * 2;
            __half2 b2 = *reinterpret_cast<const __half2*>(g_bias + col);
            __half2 v0 = __halves2half2(__float2half(acc[mi][ni][0]),
                                        __float2half(acc[mi][ni][1]));
            v0 = __hadd2(v0, b2);
            __half2 v1 = __halves2half2(__float2half(acc[mi][ni][2]),
                                        __float2half(acc[mi][ni][3]));
            v1 = __hadd2(v1, b2);
            if (f32o) {
                float* out = (float*)outv;
                *reinterpret_cast<float2*>(out + (size_t)row * EMB + col) =
                    make_float2(__low2float(v0), __high2float(v0));
                *reinterpret_cast<float2*>(out + (size_t)(row + 8) * EMB + col) =
                    make_float2(__low2float(v1), __high2float(v1));
            } else {
                __half* out = (__half*)outv;
                *reinterpret_cast<__half2*>(out + (size_t)row * EMB + col) = v0;
                *reinterpret_cast<__half2*>(out + (size_t)(row + 8) * EMB + col) = v1;
            }
        }
    }
}

// ---------------------------------------------------------------------------
extern "C" void kernel_launch(void* const* d_in, const int* in_sizes, int n_in,
                              void* d_out, int out_size) {
    const void* bigA = nullptr;
    const void* bigB = nullptr;
    const void* w    = nullptr;
    const void* bias = nullptr;
    for (int i = 0; i < n_in; i++) {
        if (in_sizes[i] == EMB)            bias = d_in[i];
        else if (in_sizes[i] == EMB * FFN) w    = d_in[i];
        else if (!bigA)                    bigA = d_in[i];
        else                               bigB = d_in[i];
    }

    static int inited = 0;
    static cudaStream_t s1;
    static cudaEvent_t evPrep[CHUNKS];
    if (!inited) {
        cudaFuncSetAttribute(gemm_k, cudaFuncAttributeMaxDynamicSharedMemorySize, SMEM_TOTAL);
        cudaStreamCreateWithFlags(&s1, cudaStreamNonBlocking);
        for (int i = 0; i < CHUNKS; i++)
            cudaEventCreateWithFlags(&evPrep[i], cudaEventDisableTiming);
        inited = 1;
    }

    dim3 grid(EMB / BN, CHUNK_ROWS / BM);   // 8 x 16 per chunk

    // prep0 (+W +bias) on capture-origin stream, then fork s1 for prep1..3
    prep_k<<<GELU_BLOCKS_CHUNK + WCONV_BLOCKS + 1, 256>>>(bigA, bigB, w, bias, 0, 1);
    cudaEventRecord(evPrep[0], 0);
    cudaStreamWaitEvent(s1, evPrep[0], 0);
    for (int c = 1; c < CHUNKS; c++) {
        prep_k<<<GELU_BLOCKS_CHUNK, 256, 0, s1>>>(bigA, bigB, w, bias,
                                                  c * CHUNK_ROWS, 0);
        cudaEventRecord(evPrep[c], s1);
    }

    // gemm chunks on origin stream; each waits its prep chunk
    gemm_k<<<grid, 256, SMEM_TOTAL>>>(d_out, bigA, bigB, 0);
    for (int c = 1; c < CHUNKS; c++) {
        cudaStreamWaitEvent(0, evPrep[c], 0);
        gemm_k<<<grid, 256, SMEM_TOTAL>>>(d_out, bigA, bigB, c * CHUNK_ROWS);
    }
}

// round 11
// speedup vs baseline: 1.1488x; 1.1488x over previous
#include <cuda_runtime.h>
#include <cuda_fp16.h>
#include <cstdint>

#define N_ROWS 8192
#define FFN    4096
#define EMB    1024

// ---------------- HMMA GEMM config (R9, known-good 172.8us) ----------------
#define BM 128
#define BN 128
#define BK 64
#define STAGES 3
#define KITERS (FFN / BK)                       // 64
#define A_STAGE_BYTES (BM * BK * 2)             // 16 KB
#define B_STAGE_BYTES (BN * BK * 2)             // 16 KB
#define STAGE_BYTES (A_STAGE_BYTES + B_STAGE_BYTES)   // 32 KB
#define SMEM_TOTAL (STAGES * STAGE_BYTES)       // 96 KB -> 2 CTAs/SM

#define GELU_BLOCKS  8192                       // 33.5M / (256*16)
#define WCONV_BLOCKS 2048                       // 4.19M / (256*8)
#define PREP_BLOCKS (GELU_BLOCKS + WCONV_BLOCKS + 1)

// Static scratch (allocation-free rule)
__device__ __align__(16) __half g_h[(size_t)N_ROWS * FFN];   // gelu(x)*mask*scale
__device__ __align__(16) __half g_w[(size_t)EMB * FFN];      // weight fp16
__device__ __align__(16) __half g_bias[EMB];

// ---------------------------------------------------------------------------
// Warp-local sniff: classify buffer order + dtype scenario from 32 words each.
// ---------------------------------------------------------------------------
__device__ __forceinline__ void sniff(const unsigned* A, const unsigned* B,
                                      int& sw, int& f32) {
    int lane = threadIdx.x & 31;
    unsigned a = __ldg(A + lane);
    unsigned b = __ldg(B + lane);
    unsigned wa = __ballot_sync(~0u, a <= 1u);
    unsigned wb = __ballot_sync(~0u, b <= 1u);
    unsigned ba = __ballot_sync(~0u, (a & 0xFEFEFEFEu) == 0u);
    unsigned bb = __ballot_sync(~0u, (b & 0xFEFEFEFEu) == 0u);
    if      (wb == ~0u) { sw = 0; f32 = 1; }
    else if (wa == ~0u) { sw = 1; f32 = 1; }
    else if (bb == ~0u) { sw = 0; f32 = 0; }
    else if (ba == ~0u) { sw = 1; f32 = 0; }
    else                { sw = 0; f32 = 1; }
}

__device__ __forceinline__ __half gelu_h(float x) {
    float g = 0.5f * x * (1.0f + erff(x * 0.70710678118654752440f));
    return __float2half(g);
}

// ---------------------------------------------------------------------------
// Prep (single launch): gelu+mask -> g_h ; weight -> g_w ; bias -> g_bias
// 16 elems/thread, all wide loads issued up front (MLP=8), no byte packing.
// ---------------------------------------------------------------------------
__global__ void __launch_bounds__(256) prep_k(const void* __restrict__ A,
                                              const void* __restrict__ B,
                                              const void* __restrict__ w,
                                              const void* __restrict__ bias) {
    int sw, f32;
    sniff((const unsigned*)A, (const unsigned*)B, sw, f32);

    const __half sc = __float2half(1.0f / 0.9f);
    const __half hz = __ushort_as_half((unsigned short)0);

    unsigned bidx = blockIdx.x;
    if (bidx < GELU_BLOCKS) {
        const char* xp = (const char*)(sw ? B : A);
        const char* mp = (const char*)(sw ? A : B);
        size_t idx = ((size_t)bidx * 256 + threadIdx.x) * 16;

        __half hs[16];
        if (f32) {
            const float4* xv4 = (const float4*)(xp + idx * 4);
            const int4*   mv4 = (const int4*)(mp + idx * 4);
            float4 xv[4]; int4 mv[4];
#pragma unroll
            for (int i = 0; i < 4; i++) xv[i] = xv4[i];   // 4 x LDG.128
#pragma unroll
            for (int i = 0; i < 4; i++) mv[i] = mv4[i];   // 4 x LDG.128
#pragma unroll
            for (int i = 0; i < 4; i++) {
                hs[i*4+0] = mv[i].x ? __hmul(gelu_h(xv[i].x), sc) : hz;
                hs[i*4+1] = mv[i].y ? __hmul(gelu_h(xv[i].y), sc) : hz;
                hs[i*4+2] = mv[i].z ? __hmul(gelu_h(xv[i].z), sc) : hz;
                hs[i*4+3] = mv[i].w ? __hmul(gelu_h(xv[i].w), sc) : hz;
            }
        } else {
            uint4 hv0 = ((const uint4*)(xp + idx * 2))[0];
            uint4 hv1 = ((const uint4*)(xp + idx * 2))[1];
            uint4 mb  = *(const uint4*)(mp + idx);
            __half xs[16];
            *reinterpret_cast<uint4*>(xs)     = hv0;
            *reinterpret_cast<uint4*>(xs + 8) = hv1;
            unsigned mw[4] = {mb.x, mb.y, mb.z, mb.w};
#pragma unroll
            for (int i = 0; i < 16; i++) {
                unsigned keep = (mw[i >> 2] >> ((i & 3) * 8)) & 0xFFu;
                hs[i] = keep ? __hmul(gelu_h(__half2float(xs[i])), sc) : hz;
            }
        }
        ((uint4*)(g_h + idx))[0] = reinterpret_cast<uint4*>(hs)[0];
        ((uint4*)(g_h + idx))[1] = reinterpret_cast<uint4*>(hs)[1];
    } else if (bidx < GELU_BLOCKS + WCONV_BLOCKS) {
        size_t i = ((size_t)(bidx - GELU_BLOCKS) * 256 + threadIdx.x) * 8;
        if (f32) {
            const float4* wv4 = (const float4*)((const float*)w + i);
            float4 v0 = wv4[0], v1 = wv4[1];
            __half h[8] = {__float2half(v0.x), __float2half(v0.y),
                           __float2half(v0.z), __float2half(v0.w),
                           __float2half(v1.x), __float2half(v1.y),
                           __float2half(v1.z), __float2half(v1.w)};
            *reinterpret_cast<uint4*>(g_w + i) = *reinterpret_cast<uint4*>(h);
        } else {
            *reinterpret_cast<uint4*>(g_w + i) = *(const uint4*)((const __half*)w + i);
        }
    } else {
        int i = threadIdx.x * 4;
        if (i < EMB) {
            if (f32) {
                float4 v = *(const float4*)((const float*)bias + i);
                __half h[4] = {__float2half(v.x), __float2half(v.y),
                               __float2half(v.z), __float2half(v.w)};
                *reinterpret_cast<uint2*>(g_bias + i) = *reinterpret_cast<uint2*>(h);
            } else {
                *reinterpret_cast<uint2*>(g_bias + i) = *(const uint2*)((const __half*)bias + i);
            }
        }
    }
}

// ---------------------------------------------------------------------------
// Pass 2: y = g_h @ g_w^T + bias  (M=8192, N=1024, K=4096)
// 256 threads = 8 warps (2x4), warp tile 64x32, 3-stage cp.async, 2 CTAs/SM.
// ---------------------------------------------------------------------------
__global__ void __launch_bounds__(256, 2) gemm_k(void* __restrict__ outv,
                                                 const void* __restrict__ A0,
                                                 const void* __restrict__ B0) {
    extern __shared__ __align__(1024) char sm[];
    const uint32_t smem_base = (uint32_t)__cvta_generic_to_shared(sm);

    int snsw, f32o;
    sniff((const unsigned*)A0, (const unsigned*)B0, snsw, f32o);

    const int tid  = threadIdx.x;
    const int lane = tid & 31;
    const int warp = tid >> 5;
    const int wm   = (warp >> 2) * 64;
    const int wn   = (warp & 3) * 32;

    const int mBase = blockIdx.y * BM;
    const int nBase = blockIdx.x * BN;

    const __half* Aglob = g_h + (size_t)mBase * FFN;
    const __half* Bglob = g_w + (size_t)nBase * FFN;

    float acc[4][4][4];
#pragma unroll
    for (int a = 0; a < 4; a++)
#pragma unroll
        for (int b = 0; b < 4; b++)
#pragma unroll
            for (int c = 0; c < 4; c++) acc[a][b][c] = 0.f;

    auto swz = [](uint32_t off) -> uint32_t { return off ^ ((off >> 3) & 0x70); };

    auto fill = [&](int kt) {
        int buf = kt % STAGES;
        uint32_t sA = smem_base + buf * STAGE_BYTES;
        uint32_t sB = sA + A_STAGE_BYTES;
        const __half* Ag = Aglob + kt * BK;
        const __half* Bg = Bglob + kt * BK;
#pragma unroll
        for (int i = 0; i < 4; i++) {
            int idx = tid + (i << 8);
            int row = idx >> 3, c = idx & 7;
            uint32_t off = (uint32_t)(row * 128 + c * 16);
            asm volatile("cp.async.cg.shared.global [%0], [%1], 16;"
                         :: "r"(sA + (off ^ ((off >> 3) & 0x70))),
                            "l"(Ag + (size_t)row * FFN + c * 8));
        }
#pragma unroll
        for (int i = 0; i < 4; i++) {
            int idx = tid + (i << 8);
            int row = idx >> 3, c = idx & 7;
            uint32_t off = (uint32_t)(row * 128 + c * 16);
            asm volatile("cp.async.cg.shared.global [%0], [%1], 16;"
                         :: "r"(sB + (off ^ ((off >> 3) & 0x70))),
                            "l"(Bg + (size_t)row * FFN + c * 8));
        }
        asm volatile("cp.async.commit_group;");
    };

    fill(0); fill(1);

    for (int kt = 0; kt < KITERS; ++kt) {
        if (kt + 1 < KITERS) asm volatile("cp.async.wait_group 1;");
        else                 asm volatile("cp.async.wait_group 0;");
        __syncthreads();

        // Prefetch early: target buffer's readers all passed the sync above.
        if (kt + STAGES - 1 < KITERS) fill(kt + STAGES - 1);

        int buf = kt % STAGES;
        uint32_t sA = smem_base + buf * STAGE_BYTES;
        uint32_t sB = sA + A_STAGE_BYTES;

#pragma unroll
        for (int ks = 0; ks < 4; ks++) {
            uint32_t a[4][4];
#pragma unroll
            for (int mi = 0; mi < 4; mi++) {
                int r = wm + mi * 16 + ((lane >> 3) & 1) * 8 + (lane & 7);
                int c = ks * 16 + (lane >> 4) * 8;
                uint32_t addr = sA + swz((uint32_t)(r * 128 + c * 2));
                asm volatile("ldmatrix.sync.aligned.m8n8.x4.shared.b16 {%0,%1,%2,%3}, [%4];"
                             : "=r"(a[mi][0]), "=r"(a[mi][1]), "=r"(a[mi][2]), "=r"(a[mi][3])
                             : "r"(addr));
            }
            uint32_t b[4][2];
#pragma unroll
            for (int nj = 0; nj < 2; nj++) {
                int r = wn + nj * 16 + (lane >> 4) * 8 + (lane & 7);
                int c = ks * 16 + ((lane >> 3) & 1) * 8;
                uint32_t addr = sB + swz((uint32_t)(r * 128 + c * 2));
                asm volatile("ldmatrix.sync.aligned.m8n8.x4.shared.b16 {%0,%1,%2,%3}, [%4];"
                             : "=r"(b[2 * nj][0]), "=r"(b[2 * nj][1]),
                               "=r"(b[2 * nj + 1][0]), "=r"(b[2 * nj + 1][1])
                             : "r"(addr));
            }
#pragma unroll
            for (int mi = 0; mi < 4; mi++)
#pragma unroll
                for (int ni = 0; ni < 4; ni++) {
                    asm volatile(
                        "mma.sync.aligned.m16n8k16.row.col.f32.f16.f16.f32 "
                        "{%0,%1,%2,%3}, {%4,%5,%6,%7}, {%8,%9}, {%0,%1,%2,%3};"
                        : "+f"(acc[mi][ni][0]), "+f"(acc[mi][ni][1]),
                          "+f"(acc[mi][ni][2]), "+f"(acc[mi][ni][3])
                        : "r"(a[mi][0]), "r"(a[mi][1]), "r"(a[mi][2]), "r"(a[mi][3]),
                          "r"(b[ni][0]), "r"(b[ni][1]));
                }
        }
    }

    // Epilogue: fp16(acc) + fp16 bias, store per __output__ dtype
#pragma unroll
    for (int mi = 0; mi < 4; mi++) {
#pragma unroll
        for (int ni = 0; ni < 4; ni++) {
            int row = mBase + wm + mi * 16 + (lane >> 2);
            int col = nBase + wn + ni * 8 + (lane & 3) * 2;
            __half2 b2 = *reinterpret_cast<const __half2*>(g_bias + col);
            __half2 v0 = __halves2half2(__float2half(acc[mi][ni][0]),
                                        __float2half(acc[mi][ni][1]));
            v0 = __hadd2(v0, b2);
            __half2 v1 = __halves2half2(__float2half(acc[mi][ni][2]),
                                        __float2half(acc[mi][ni][3]));
            v1 = __hadd2(v1, b2);
            if (f32o) {
                float* out = (float*)outv;
                *reinterpret_cast<float2*>(out + (size_t)row * EMB + col) =
                    make_float2(__low2float(v0), __high2float(v0));
                *reinterpret_cast<float2*>(out + (size_t)(row + 8) * EMB + col) =
                    make_float2(__low2float(v1), __high2float(v1));
            } else {
                __half* out = (__half*)outv;
                *reinterpret_cast<__half2*>(out + (size_t)row * EMB + col) = v0;
                *reinterpret_cast<__half2*>(out + (size_t)(row + 8) * EMB + col) = v1;
            }
        }
    }
}

// ---------------------------------------------------------------------------
extern "C" void kernel_launch(void* const* d_in, const int* in_sizes, int n_in,
                              void* d_out, int out_size) {
    const void* bigA = nullptr;
    const void* bigB = nullptr;
    const void* w    = nullptr;
    const void* bias = nullptr;
    for (int i = 0; i < n_in; i++) {
        if (in_sizes[i] == EMB)            bias = d_in[i];
        else if (in_sizes[i] == EMB * FFN) w    = d_in[i];
        else if (!bigA)                    bigA = d_in[i];
        else                               bigB = d_in[i];
    }

    prep_k<<<PREP_BLOCKS, 256>>>(bigA, bigB, w, bias);

    static int smem_set = 0;
    if (!smem_set) {
        cudaFuncSetAttribute(gemm_k, cudaFuncAttributeMaxDynamicSharedMemorySize, SMEM_TOTAL);
        smem_set = 1;
    }
    dim3 grid(EMB / BN, N_ROWS / BM);   // 8 x 64 = 512 CTAs, n-tiles fast
    gemm_k<<<grid, 256, SMEM_TOTAL>>>(d_out, bigA, bigB);
}

// round 12
// speedup vs baseline: 1.2716x; 1.1069x over previous
#include <cuda_runtime.h>
#include <cuda_fp16.h>
#include <cstdint>

#define N_ROWS 8192
#define FFN    4096
#define EMB    1024

// ---------------- HMMA GEMM config (R9, known-good 172.8us) ----------------
#define BM 128
#define BN 128
#define BK 64
#define STAGES 3
#define KITERS (FFN / BK)                       // 64
#define A_STAGE_BYTES (BM * BK * 2)             // 16 KB
#define B_STAGE_BYTES (BN * BK * 2)             // 16 KB
#define STAGE_BYTES (A_STAGE_BYTES + B_STAGE_BYTES)   // 32 KB
#define SMEM_TOTAL (STAGES * STAGE_BYTES)       // 96 KB -> 2 CTAs/SM

#define GELU_BLOCKS  8192                       // 33.5M / (256*16)
#define WCONV_BLOCKS 2048                       // 4.19M / (256*8)
#define PREP_BLOCKS (GELU_BLOCKS + WCONV_BLOCKS + 1)

// Static scratch (allocation-free rule)
__device__ __align__(16) __half g_h[(size_t)N_ROWS * FFN];   // gelu(x)*mask*scale
__device__ __align__(16) __half g_w[(size_t)EMB * FFN];      // weight fp16
__device__ __align__(16) __half g_bias[EMB];

// ---------------------------------------------------------------------------
// Warp-local sniff: classify buffer order + dtype scenario from 32 words each.
// ---------------------------------------------------------------------------
__device__ __forceinline__ void sniff(const unsigned* A, const unsigned* B,
                                      int& sw, int& f32) {
    int lane = threadIdx.x & 31;
    unsigned a = __ldg(A + lane);
    unsigned b = __ldg(B + lane);
    unsigned wa = __ballot_sync(~0u, a <= 1u);
    unsigned wb = __ballot_sync(~0u, b <= 1u);
    unsigned ba = __ballot_sync(~0u, (a & 0xFEFEFEFEu) == 0u);
    unsigned bb = __ballot_sync(~0u, (b & 0xFEFEFEFEu) == 0u);
    if      (wb == ~0u) { sw = 0; f32 = 1; }
    else if (wa == ~0u) { sw = 1; f32 = 1; }
    else if (bb == ~0u) { sw = 0; f32 = 0; }
    else if (ba == ~0u) { sw = 1; f32 = 0; }
    else                { sw = 0; f32 = 1; }
}

// GELU, tanh-form with HW tanh.approx.f32 (~6 ops vs ~15 for erff).
// 0.5x(1+tanh(0.7978845608(x + 0.044715 x^3)))
__device__ __forceinline__ __half gelu_h(float x) {
    float u = 0.7978845608028654f * fmaf(0.044715f * x, x * x, x);
    float t;
    asm("tanh.approx.f32 %0, %1;" : "=f"(t) : "f"(u));
    return __float2half(0.5f * x * (1.0f + t));
}

// ---------------------------------------------------------------------------
// Prep (single launch): gelu+mask -> g_h ; weight -> g_w ; bias -> g_bias
// ---------------------------------------------------------------------------
__global__ void __launch_bounds__(256) prep_k(const void* __restrict__ A,
                                              const void* __restrict__ B,
                                              const void* __restrict__ w,
                                              const void* __restrict__ bias) {
    int sw, f32;
    sniff((const unsigned*)A, (const unsigned*)B, sw, f32);

    const __half sc = __float2half(1.0f / 0.9f);
    const __half hz = __ushort_as_half((unsigned short)0);

    unsigned bidx = blockIdx.x;
    if (bidx < GELU_BLOCKS) {
        const char* xp = (const char*)(sw ? B : A);
        const char* mp = (const char*)(sw ? A : B);
        size_t idx = ((size_t)bidx * 256 + threadIdx.x) * 16;

        __half hs[16];
        if (f32) {
            const float4* xv4 = (const float4*)(xp + idx * 4);
            const int4*   mv4 = (const int4*)(mp + idx * 4);
            float4 xv[4]; int4 mv[4];
#pragma unroll
            for (int i = 0; i < 4; i++) xv[i] = xv4[i];   // 4 x LDG.128
#pragma unroll
            for (int i = 0; i < 4; i++) mv[i] = mv4[i];   // 4 x LDG.128
#pragma unroll
            for (int i = 0; i < 4; i++) {
                hs[i*4+0] = mv[i].x ? __hmul(gelu_h(xv[i].x), sc) : hz;
                hs[i*4+1] = mv[i].y ? __hmul(gelu_h(xv[i].y), sc) : hz;
                hs[i*4+2] = mv[i].z ? __hmul(gelu_h(xv[i].z), sc) : hz;
                hs[i*4+3] = mv[i].w ? __hmul(gelu_h(xv[i].w), sc) : hz;
            }
        } else {
            uint4 hv0 = ((const uint4*)(xp + idx * 2))[0];
            uint4 hv1 = ((const uint4*)(xp + idx * 2))[1];
            uint4 mb  = *(const uint4*)(mp + idx);
            __half xs[16];
            *reinterpret_cast<uint4*>(xs)     = hv0;
            *reinterpret_cast<uint4*>(xs + 8) = hv1;
            unsigned mw[4] = {mb.x, mb.y, mb.z, mb.w};
#pragma unroll
            for (int i = 0; i < 16; i++) {
                unsigned keep = (mw[i >> 2] >> ((i & 3) * 8)) & 0xFFu;
                hs[i] = keep ? __hmul(gelu_h(__half2float(xs[i])), sc) : hz;
            }
        }
        ((uint4*)(g_h + idx))[0] = reinterpret_cast<uint4*>(hs)[0];
        ((uint4*)(g_h + idx))[1] = reinterpret_cast<uint4*>(hs)[1];
    } else if (bidx < GELU_BLOCKS + WCONV_BLOCKS) {
        size_t i = ((size_t)(bidx - GELU_BLOCKS) * 256 + threadIdx.x) * 8;
        if (f32) {
            const float4* wv4 = (const float4*)((const float*)w + i);
            float4 v0 = wv4[0], v1 = wv4[1];
            __half h[8] = {__float2half(v0.x), __float2half(v0.y),
                           __float2half(v0.z), __float2half(v0.w),
                           __float2half(v1.x), __float2half(v1.y),
                           __float2half(v1.z), __float2half(v1.w)};
            *reinterpret_cast<uint4*>(g_w + i) = *reinterpret_cast<uint4*>(h);
        } else {
            *reinterpret_cast<uint4*>(g_w + i) = *(const uint4*)((const __half*)w + i);
        }
    } else {
        int i = threadIdx.x * 4;
        if (i < EMB) {
            if (f32) {
                float4 v = *(const float4*)((const float*)bias + i);
                __half h[4] = {__float2half(v.x), __float2half(v.y),
                               __float2half(v.z), __float2half(v.w)};
                *reinterpret_cast<uint2*>(g_bias + i) = *reinterpret_cast<uint2*>(h);
            } else {
                *reinterpret_cast<uint2*>(g_bias + i) = *(const uint2*)((const __half*)bias + i);
            }
        }
    }
}

// ---------------------------------------------------------------------------
// Pass 2: y = g_h @ g_w^T + bias  (M=8192, N=1024, K=4096)
// 256 threads = 8 warps (2x4), warp tile 64x32, 3-stage cp.async, 2 CTAs/SM.
// fill() AFTER the compute block (R9 ordering — measured 23us faster than
// prefetch-early; cp.async bursts must not precede the ldmatrix stream).
// ---------------------------------------------------------------------------
__global__ void __launch_bounds__(256, 2) gemm_k(void* __restrict__ outv,
                                                 const void* __restrict__ A0,
                                                 const void* __restrict__ B0) {
    extern __shared__ __align__(1024) char sm[];
    const uint32_t smem_base = (uint32_t)__cvta_generic_to_shared(sm);

    int snsw, f32o;
    sniff((const unsigned*)A0, (const unsigned*)B0, snsw, f32o);

    const int tid  = threadIdx.x;
    const int lane = tid & 31;
    const int warp = tid >> 5;
    const int wm   = (warp >> 2) * 64;
    const int wn   = (warp & 3) * 32;

    const int mBase = blockIdx.y * BM;
    const int nBase = blockIdx.x * BN;

    const __half* Aglob = g_h + (size_t)mBase * FFN;
    const __half* Bglob = g_w + (size_t)nBase * FFN;

    float acc[4][4][4];
#pragma unroll
    for (int a = 0; a < 4; a++)
#pragma unroll
        for (int b = 0; b < 4; b++)
#pragma unroll
            for (int c = 0; c < 4; c++) acc[a][b][c] = 0.f;

    auto swz = [](uint32_t off) -> uint32_t { return off ^ ((off >> 3) & 0x70); };

    auto fill = [&](int kt) {
        int buf = kt % STAGES;
        uint32_t sA = smem_base + buf * STAGE_BYTES;
        uint32_t sB = sA + A_STAGE_BYTES;
        const __half* Ag = Aglob + kt * BK;
        const __half* Bg = Bglob + kt * BK;
#pragma unroll
        for (int i = 0; i < 4; i++) {
            int idx = tid + (i << 8);
            int row = idx >> 3, c = idx & 7;
            uint32_t off = (uint32_t)(row * 128 + c * 16);
            asm volatile("cp.async.cg.shared.global [%0], [%1], 16;"
                         :: "r"(sA + (off ^ ((off >> 3) & 0x70))),
                            "l"(Ag + (size_t)row * FFN + c * 8));
        }
#pragma unroll
        for (int i = 0; i < 4; i++) {
            int idx = tid + (i << 8);
            int row = idx >> 3, c = idx & 7;
            uint32_t off = (uint32_t)(row * 128 + c * 16);
            asm volatile("cp.async.cg.shared.global [%0], [%1], 16;"
                         :: "r"(sB + (off ^ ((off >> 3) & 0x70))),
                            "l"(Bg + (size_t)row * FFN + c * 8));
        }
        asm volatile("cp.async.commit_group;");
    };

    fill(0); fill(1);

    for (int kt = 0; kt < KITERS; ++kt) {
        if (kt + 1 < KITERS) asm volatile("cp.async.wait_group 1;");
        else                 asm volatile("cp.async.wait_group 0;");
        __syncthreads();

        int buf = kt % STAGES;
        uint32_t sA = smem_base + buf * STAGE_BYTES;
        uint32_t sB = sA + A_STAGE_BYTES;

#pragma unroll
        for (int ks = 0; ks < 4; ks++) {
            uint32_t a[4][4];
#pragma unroll
            for (int mi = 0; mi < 4; mi++) {
                int r = wm + mi * 16 + ((lane >> 3) & 1) * 8 + (lane & 7);
                int c = ks * 16 + (lane >> 4) * 8;
                uint32_t addr = sA + swz((uint32_t)(r * 128 + c * 2));
                asm volatile("ldmatrix.sync.aligned.m8n8.x4.shared.b16 {%0,%1,%2,%3}, [%4];"
                             : "=r"(a[mi][0]), "=r"(a[mi][1]), "=r"(a[mi][2]), "=r"(a[mi][3])
                             : "r"(addr));
            }
            uint32_t b[4][2];
#pragma unroll
            for (int nj = 0; nj < 2; nj++) {
                int r = wn + nj * 16 + (lane >> 4) * 8 + (lane & 7);
                int c = ks * 16 + ((lane >> 3) & 1) * 8;
                uint32_t addr = sB + swz((uint32_t)(r * 128 + c * 2));
                asm volatile("ldmatrix.sync.aligned.m8n8.x4.shared.b16 {%0,%1,%2,%3}, [%4];"
                             : "=r"(b[2 * nj][0]), "=r"(b[2 * nj][1]),
                               "=r"(b[2 * nj + 1][0]), "=r"(b[2 * nj + 1][1])
                             : "r"(addr));
            }
#pragma unroll
            for (int mi = 0; mi < 4; mi++)
#pragma unroll
                for (int ni = 0; ni < 4; ni++) {
                    asm volatile(
                        "mma.sync.aligned.m16n8k16.row.col.f32.f16.f16.f32 "
                        "{%0,%1,%2,%3}, {%4,%5,%6,%7}, {%8,%9}, {%0,%1,%2,%3};"
                        : "+f"(acc[mi][ni][0]), "+f"(acc[mi][ni][1]),
                          "+f"(acc[mi][ni][2]), "+f"(acc[mi][ni][3])
                        : "r"(a[mi][0]), "r"(a[mi][1]), "r"(a[mi][2]), "r"(a[mi][3]),
                          "r"(b[ni][0]), "r"(b[ni][1]));
                }
        }
        if (kt + STAGES - 1 < KITERS) fill(kt + STAGES - 1);
    }

    // Epilogue: fp16(acc) + fp16 bias, store per __output__ dtype
#pragma unroll
    for (int mi = 0; mi < 4; mi++) {
#pragma unroll
        for (int ni = 0; ni < 4; ni++) {
            int row = mBase + wm + mi * 16 + (lane >> 2);
            int col = nBase + wn + ni * 8 + (lane & 3) * 2;
            __half2 b2 = *reinterpret_cast<const __half2*>(g_bias + col);
            __half2 v0 = __halves2half2(__float2half(acc[mi][ni][0]),
                                        __float2half(acc[mi][ni][1]));
            v0 = __hadd2(v0, b2);
            __half2 v1 = __halves2half2(__float2half(acc[mi][ni][2]),
                                        __float2half(acc[mi][ni][3]));
            v1 = __hadd2(v1, b2);
            if (f32o) {
                float* out = (float*)outv;
                *reinterpret_cast<float2*>(out + (size_t)row * EMB + col) =
                    make_float2(__low2float(v0), __high2float(v0));
                *reinterpret_cast<float2*>(out + (size_t)(row + 8) * EMB + col) =
                    make_float2(__low2float(v1), __high2float(v1));
            } else {
                __half* out = (__half*)outv;
                *reinterpret_cast<__half2*>(out + (size_t)row * EMB + col) = v0;
                *reinterpret_cast<__half2*>(out + (size_t)(row + 8) * EMB + col) = v1;
            }
        }
    }
}

// ---------------------------------------------------------------------------
extern "C" void kernel_launch(void* const* d_in, const int* in_sizes, int n_in,
                              void* d_out, int out_size) {
    const void* bigA = nullptr;
    const void* bigB = nullptr;
    const void* w    = nullptr;
    const void* bias = nullptr;
    for (int i = 0; i < n_in; i++) {
        if (in_sizes[i] == EMB)            bias = d_in[i];
        else if (in_sizes[i] == EMB * FFN) w    = d_in[i];
        else if (!bigA)                    bigA = d_in[i];
        else                               bigB = d_in[i];
    }

    prep_k<<<PREP_BLOCKS, 256>>>(bigA, bigB, w, bias);

    static int smem_set = 0;
    if (!smem_set) {
        cudaFuncSetAttribute(gemm_k, cudaFuncAttributeMaxDynamicSharedMemorySize, SMEM_TOTAL);
        smem_set = 1;
    }
    dim3 grid(EMB / BN, N_ROWS / BM);   // 8 x 64 = 512 CTAs, n-tiles fast
    gemm_k<<<grid, 256, SMEM_TOTAL>>>(d_out, bigA, bigB);
}